// round 7
// baseline (speedup 1.0000x reference)
#include <cuda_runtime.h>
#include <cuda_bf16.h>

// CenterLoss: loss = (1/(B*C)) * sum_i ||x_i - centers[labels_i]||^2
// B=4096, C=20000, D=128. Gather + reduce, single launch.
//
// 128 blocks x 1024 threads, ONE row per warp -> 4096 warps, all resident in
// a single wave (1 block/SM on 128 of 148 SMs). Every label load and x load
// is in flight grid-wide at once; center gathers follow one dependent trip
// later. Cross-block reduction is one relaxed u64 atomicAdd per block
// carrying ticket (bits[63:50]) + 16.34 fixed-point partial (bits[49:0]);
// integer adds => bit-exact deterministic across replays. Last block writes
// the output and resets the accumulator for the next graph replay.

#define CL_BATCH 4096
#define CL_FEAT 128
#define CL_NCLASSES 20000
#define CL_WARPS 32
#define CL_THREADS (CL_WARPS * 32)                 // 1024
#define CL_ROWS_PER_BLOCK CL_WARPS                 // one row per warp
#define CL_NBLOCKS (CL_BATCH / CL_ROWS_PER_BLOCK)  // 128

#define CL_TICKET_SHIFT 50
#define CL_SUM_MASK ((1ULL << CL_TICKET_SHIFT) - 1ULL)
#define CL_FIXED_SCALE 65536.0f  // 2^16 fractional bits

__device__ unsigned long long cl_g_acc = 0ULL;

__global__ void __launch_bounds__(CL_THREADS, 1) cl_fused_kernel(
    const float* __restrict__ x,
    const int* __restrict__ labels,
    const float* __restrict__ centers,
    float* __restrict__ out)
{
    const int warp = threadIdx.x >> 5;
    const int lane = threadIdx.x & 31;
    const int row = blockIdx.x * CL_ROWS_PER_BLOCK + warp;

    // Head of the dependent chain: issue ASAP.
    const int lab = __ldg(&labels[row]);

    const float4* __restrict__ xr = reinterpret_cast<const float4*>(x + (size_t)row * CL_FEAT);
    float4 xv = xr[lane];  // independent of label, overlaps with it

    const float4* __restrict__ cr = reinterpret_cast<const float4*>(centers + (size_t)lab * CL_FEAT);
    float4 cv = cr[lane];  // one trip after label

    float dx = xv.x - cv.x;
    float dy = xv.y - cv.y;
    float dz = xv.z - cv.z;
    float dw = xv.w - cv.w;
    float s = dx * dx + dy * dy + dz * dz + dw * dw;

    // warp reduction
    #pragma unroll
    for (int o = 16; o > 0; o >>= 1)
        s += __shfl_xor_sync(0xffffffffu, s, o);

    __shared__ float sm[CL_WARPS];
    if (lane == 0) sm[warp] = s;
    __syncthreads();

    if (warp == 0) {
        // warp 0 reduces the 32 per-warp sums with a shuffle tree.
        float t = sm[lane];
        #pragma unroll
        for (int o = 16; o > 0; o >>= 1)
            t += __shfl_xor_sync(0xffffffffu, t, o);

        if (lane == 0) {
            // Pack ticket + fixed-point partial into one u64 atomic.
            // Block partial ~ 4.6e3 -> fixed ~ 3e8; total ~ 3.9e10 << 2^50.
            unsigned long long pkt =
                (1ULL << CL_TICKET_SHIFT) | __float2ull_rn(t * CL_FIXED_SCALE);

            unsigned long long old = atomicAdd(&cl_g_acc, pkt);

            if ((old >> CL_TICKET_SHIFT) == (unsigned long long)(CL_NBLOCKS - 1)) {
                unsigned long long total = (old + pkt) & CL_SUM_MASK;
                const float inv = 1.0f / ((float)CL_BATCH * (float)CL_NCLASSES);
                *out = (float)total * (1.0f / CL_FIXED_SCALE) * inv;
                // Self-reset for the next graph replay.
                atomicExch(&cl_g_acc, 0ULL);
            }
        }
    }
}

extern "C" void kernel_launch(void* const* d_in, const int* in_sizes, int n_in,
                              void* d_out, int out_size)
{
    const float* x       = (const float*)d_in[0];
    const int*   labels  = (const int*)d_in[1];
    const float* centers = (const float*)d_in[2];
    float* out = (float*)d_out;

    cl_fused_kernel<<<CL_NBLOCKS, CL_THREADS>>>(x, labels, centers, out);
}

// round 8
// speedup vs baseline: 1.1106x; 1.1106x over previous
#include <cuda_runtime.h>
#include <cuda_bf16.h>

// CenterLoss: loss = (1/(B*C)) * sum_i ||x_i - centers[labels_i]||^2
// B=4096, C=20000, D=128. Gather + reduce, single launch.
//
// Proven-best structure (R6): 512 blocks x 256 threads, one row per warp.
// Cross-block reduction via ONE relaxed u64 atomicAdd per block carrying a
// ticket (bits [63:50]) + 16.34 fixed-point partial (bits [49:0]). Integer
// adds are associative -> bit-exact deterministic across graph replays.
// Last block (ticket == NBLOCKS-1) owns the total in-register, writes the
// output, and resets the accumulator with a plain store (sole accessor).
//
// Micro-deltas vs R6: shuffle-tree block reduce (replaces serial LDS chain),
// plain-store accumulator reset (replaces atomicExch RMW).

#define CL_BATCH 4096
#define CL_FEAT 128
#define CL_NCLASSES 20000
#define CL_WARPS 8
#define CL_THREADS (CL_WARPS * 32)                 // 256
#define CL_ROWS_PER_BLOCK CL_WARPS                 // one row per warp
#define CL_NBLOCKS (CL_BATCH / CL_ROWS_PER_BLOCK)  // 512

#define CL_TICKET_SHIFT 50
#define CL_SUM_MASK ((1ULL << CL_TICKET_SHIFT) - 1ULL)
#define CL_FIXED_SCALE 65536.0f  // 2^16 fractional bits

__device__ unsigned long long cl_g_acc = 0ULL;

__global__ void __launch_bounds__(CL_THREADS) cl_fused_kernel(
    const float* __restrict__ x,
    const int* __restrict__ labels,
    const float* __restrict__ centers,
    float* __restrict__ out)
{
    const int warp = threadIdx.x >> 5;
    const int lane = threadIdx.x & 31;
    const int row = blockIdx.x * CL_ROWS_PER_BLOCK + warp;

    // Head of the dependent chain: issue ASAP.
    const int lab = __ldg(&labels[row]);

    const float4* __restrict__ xr = reinterpret_cast<const float4*>(x + (size_t)row * CL_FEAT);
    float4 xv = xr[lane];  // independent of label, overlaps its latency

    const float4* __restrict__ cr = reinterpret_cast<const float4*>(centers + (size_t)lab * CL_FEAT);
    float4 cv = cr[lane];  // one dependent trip after label

    float dx = xv.x - cv.x;
    float dy = xv.y - cv.y;
    float dz = xv.z - cv.z;
    float dw = xv.w - cv.w;
    float s = dx * dx + dy * dy + dz * dz + dw * dw;

    // warp reduction
    #pragma unroll
    for (int o = 16; o > 0; o >>= 1)
        s += __shfl_xor_sync(0xffffffffu, s, o);

    __shared__ float sm[CL_WARPS];
    if (lane == 0) sm[warp] = s;
    __syncthreads();

    if (warp == 0) {
        // Shuffle-tree reduce of the 8 per-warp sums (lanes 0..7).
        float t = (lane < CL_WARPS) ? sm[lane] : 0.0f;
        #pragma unroll
        for (int o = 4; o > 0; o >>= 1)
            t += __shfl_xor_sync(0xffffffffu, t, o);

        if (lane == 0) {
            // Pack ticket + fixed-point partial into one relaxed u64 atomic.
            // Block partial ~ 1.1e3 -> fixed ~ 7.5e7; 512 blocks ~ 3.9e10 << 2^50.
            unsigned long long pkt =
                (1ULL << CL_TICKET_SHIFT) | __float2ull_rn(t * CL_FIXED_SCALE);

            unsigned long long old = atomicAdd(&cl_g_acc, pkt);

            if ((old >> CL_TICKET_SHIFT) == (unsigned long long)(CL_NBLOCKS - 1)) {
                unsigned long long total = (old + pkt) & CL_SUM_MASK;
                const float inv = 1.0f / ((float)CL_BATCH * (float)CL_NCLASSES);
                *out = (float)total * (1.0f / CL_FIXED_SCALE) * inv;
                // Sole accessor at this point; plain store resets for the
                // next replay (ordered by the kernel boundary).
                cl_g_acc = 0ULL;
            }
        }
    }
}

extern "C" void kernel_launch(void* const* d_in, const int* in_sizes, int n_in,
                              void* d_out, int out_size)
{
    const float* x       = (const float*)d_in[0];
    const int*   labels  = (const int*)d_in[1];
    const float* centers = (const float*)d_in[2];
    float* out = (float*)d_out;

    cl_fused_kernel<<<CL_NBLOCKS, CL_THREADS>>>(x, labels, centers, out);
}

// round 9
// speedup vs baseline: 1.1159x; 1.0048x over previous
#include <cuda_runtime.h>
#include <cuda_bf16.h>

// CenterLoss: loss = (1/(B*C)) * sum_i ||x_i - centers[labels_i]||^2
// B=4096, C=20000, D=128. Gather + reduce, single launch.
//
// 1024 blocks x 128 threads (4 warps), one row per warp -> 4096 warps total
// (same parallelism as the 6.62us best), but smaller CTAs: less intra-block
// barrier skew, finer SM load balance (6.9 CTAs/SM), shorter per-CTA tail.
//
// Cross-block reduction: ONE relaxed u64 atomicAdd per block carrying a
// ticket (bits [63:50]) + 16.34 fixed-point partial (bits [49:0]). Integer
// adds are associative -> bit-exact deterministic across graph replays.
// Last block (ticket == NBLOCKS-1) holds the total in-register, writes the
// output, and resets the accumulator with a plain store (sole accessor;
// next replay is ordered by the kernel boundary).

#define CL_BATCH 4096
#define CL_FEAT 128
#define CL_NCLASSES 20000
#define CL_WARPS 4
#define CL_THREADS (CL_WARPS * 32)                 // 128
#define CL_ROWS_PER_BLOCK CL_WARPS                 // one row per warp
#define CL_NBLOCKS (CL_BATCH / CL_ROWS_PER_BLOCK)  // 1024

#define CL_TICKET_SHIFT 50
#define CL_SUM_MASK ((1ULL << CL_TICKET_SHIFT) - 1ULL)
#define CL_FIXED_SCALE 65536.0f  // 2^16 fractional bits

__device__ unsigned long long cl_g_acc = 0ULL;

__global__ void __launch_bounds__(CL_THREADS) cl_fused_kernel(
    const float* __restrict__ x,
    const int* __restrict__ labels,
    const float* __restrict__ centers,
    float* __restrict__ out)
{
    const int warp = threadIdx.x >> 5;
    const int lane = threadIdx.x & 31;
    const int row = blockIdx.x * CL_ROWS_PER_BLOCK + warp;

    // Head of the dependent chain: issue ASAP (broadcast load, 1 sector).
    const int lab = __ldg(&labels[row]);

    const float4* __restrict__ xr = reinterpret_cast<const float4*>(x + (size_t)row * CL_FEAT);
    float4 xv = xr[lane];  // independent of label, overlaps its latency

    const float4* __restrict__ cr = reinterpret_cast<const float4*>(centers + (size_t)lab * CL_FEAT);
    float4 cv = cr[lane];  // one dependent trip after label

    float dx = xv.x - cv.x;
    float dy = xv.y - cv.y;
    float dz = xv.z - cv.z;
    float dw = xv.w - cv.w;
    float s = dx * dx + dy * dy + dz * dz + dw * dw;

    // warp reduction
    #pragma unroll
    for (int o = 16; o > 0; o >>= 1)
        s += __shfl_xor_sync(0xffffffffu, s, o);

    __shared__ float sm[CL_WARPS];
    if (lane == 0) sm[warp] = s;
    __syncthreads();

    if (warp == 0) {
        // Shuffle-tree reduce of the 4 per-warp sums (lanes 0..3).
        float t = (lane < CL_WARPS) ? sm[lane] : 0.0f;
        #pragma unroll
        for (int o = 2; o > 0; o >>= 1)
            t += __shfl_xor_sync(0xffffffffu, t, o);

        if (lane == 0) {
            // Block partial ~ 570 -> fixed ~ 3.7e7; 1024 blocks ~ 3.9e10 << 2^50.
            unsigned long long pkt =
                (1ULL << CL_TICKET_SHIFT) | __float2ull_rn(t * CL_FIXED_SCALE);

            unsigned long long old = atomicAdd(&cl_g_acc, pkt);

            if ((old >> CL_TICKET_SHIFT) == (unsigned long long)(CL_NBLOCKS - 1)) {
                unsigned long long total = (old + pkt) & CL_SUM_MASK;
                const float inv = 1.0f / ((float)CL_BATCH * (float)CL_NCLASSES);
                *out = (float)total * (1.0f / CL_FIXED_SCALE) * inv;
                // Sole accessor at this point; plain store resets for replay.
                cl_g_acc = 0ULL;
            }
        }
    }
}

extern "C" void kernel_launch(void* const* d_in, const int* in_sizes, int n_in,
                              void* d_out, int out_size)
{
    const float* x       = (const float*)d_in[0];
    const int*   labels  = (const int*)d_in[1];
    const float* centers = (const float*)d_in[2];
    float* out = (float*)d_out;

    cl_fused_kernel<<<CL_NBLOCKS, CL_THREADS>>>(x, labels, centers, out);
}